// round 15
// baseline (speedup 1.0000x reference)
#include <cuda_runtime.h>
#include <math.h>
#include <stdint.h>

#define B_  2
#define T_  2048
#define C_  1024
#define H_  16
#define DH_ 64
#define BT_ (B_*T_)
#define FF_ (4*C_)
#define S3_ (3*C_)
// exp2 scale: (C^-0.5) * log2(e) = (1/32)*1.4426950408889634
#define ESC 0.045084220027780106f

// ------------------- device scratch -------------------
__device__ float g_h    [BT_*C_];
__device__ float g_qkv  [(size_t)BT_*S3_];
__device__ float g_o    [BT_*C_];
__device__ float g_h2   [BT_*C_];
__device__ float g_ff   [(size_t)BT_*FF_];
__device__ float g_WqkvT[(size_t)S3_*C_];   // [N=3C][K=C]
__device__ float g_WoT  [(size_t)C_*C_];    // [N=C][K=C]
__device__ float g_W1T  [(size_t)FF_*C_];   // [N=FF][K=C]
__device__ float g_W2T  [(size_t)C_*FF_];   // [N=C][K=FF]

// ------------------- helpers -------------------
__device__ __forceinline__ float to_tf32(float x) {
    uint32_t u; asm("cvt.rna.tf32.f32 %0, %1;" : "=r"(u) : "f"(x));
    return __uint_as_float(u);
}
__device__ __forceinline__ uint32_t tf32u(float x) {
    uint32_t u; asm("cvt.rna.tf32.f32 %0, %1;" : "=r"(u) : "f"(x));
    return u;
}
__device__ __forceinline__ void mma_tf32(float* c, const uint32_t* a, const uint32_t* b) {
    asm volatile(
        "mma.sync.aligned.m16n8k8.row.col.f32.tf32.tf32.f32 "
        "{%0,%1,%2,%3}, {%4,%5,%6,%7}, {%8,%9}, {%0,%1,%2,%3};"
        : "+f"(c[0]), "+f"(c[1]), "+f"(c[2]), "+f"(c[3])
        : "r"(a[0]), "r"(a[1]), "r"(a[2]), "r"(a[3]), "r"(b[0]), "r"(b[1]));
}
__device__ __forceinline__ void cp16(void* sptr, const void* gptr) {
    uint32_t s = (uint32_t)__cvta_generic_to_shared(sptr);
    asm volatile("cp.async.ca.shared.global [%0], [%1], 16;" :: "r"(s), "l"(gptr));
}
__device__ __forceinline__ void cp_commit() { asm volatile("cp.async.commit_group;"); }
template<int N> __device__ __forceinline__ void cp_wait() {
    asm volatile("cp.async.wait_group %0;" :: "n"(N));
}

__device__ __forceinline__ float block_reduce_sum(float v) {
    __shared__ float sm[8];
    __shared__ float res;
    #pragma unroll
    for (int o = 16; o; o >>= 1) v += __shfl_xor_sync(0xffffffffu, v, o);
    if ((threadIdx.x & 31) == 0) sm[threadIdx.x >> 5] = v;
    __syncthreads();
    if (threadIdx.x < 32) {
        float t = (threadIdx.x < 8) ? sm[threadIdx.x] : 0.f;
        #pragma unroll
        for (int o = 4; o; o >>= 1) t += __shfl_xor_sync(0xffffffffu, t, o);
        if (threadIdx.x == 0) res = t;
    }
    __syncthreads();
    return res;
}

// ------------------- merged weight prep + LN1 (single launch) ------------------
__global__ void __launch_bounds__(256)
prep_ln(const float* __restrict__ Wq, const float* __restrict__ Wk,
        const float* __restrict__ Wv, const float* __restrict__ Wo,
        const float* __restrict__ W1, const float* __restrict__ W2,
        float* __restrict__ wqkvT, float* __restrict__ woT,
        float* __restrict__ w1T,   float* __restrict__ w2T,
        const float* __restrict__ x, const float* __restrict__ g1,
        const float* __restrict__ be1, float* __restrict__ h) {
    int tile = blockIdx.x;

    if (tile >= 12288) {                    // ---- LN1 row ----
        size_t row = tile - 12288;
        const float* xr = x + row * C_;
        float v[4]; float s = 0.f;
        #pragma unroll
        for (int i = 0; i < 4; i++) { v[i] = xr[threadIdx.x + i*256]; s += v[i]; }
        float mu = block_reduce_sum(s) * (1.f / C_);
        float s2 = 0.f;
        #pragma unroll
        for (int i = 0; i < 4; i++) { float d = v[i] - mu; s2 += d * d; }
        float rstd = rsqrtf(block_reduce_sum(s2) * (1.f / C_) + 1e-5f);
        float* orow = h + row * C_;
        #pragma unroll
        for (int i = 0; i < 4; i++) {
            int j = threadIdx.x + i*256;
            orow[j] = to_tf32((v[i] - mu) * rstd * g1[j] + be1[j]);
        }
        return;
    }

    __shared__ float t[32][33];
    int tx = threadIdx.x & 31, ty = threadIdx.x >> 5;

    if (tile < 3072) {                      // ---- qkv repack-transpose ----
        int bx = tile % 96, by = tile / 96;
        int k0 = by*32, n0 = bx*32;
        int n = n0 + tx;
        const float* W = (n < C_) ? Wq : ((n < 2*C_) ? Wk : Wv);
        int nn = n % C_;
        #pragma unroll
        for (int i = ty; i < 32; i += 8)
            t[i][tx] = W[((size_t)(nn/DH_)*C_ + (k0+i))*DH_ + (nn%DH_)];
        __syncthreads();
        #pragma unroll
        for (int i = ty; i < 32; i += 8)
            wqkvT[(size_t)(n0+i)*C_ + k0 + tx] = to_tf32(t[tx][i]);
        return;
    }
    const float* in; float* out; int K, N, bx, by;
    if (tile < 4096)      { int r = tile-3072; in=Wo; out=woT; K=C_;  N=C_;  bx=r%32;  by=r/32;  }
    else if (tile < 8192) { int r = tile-4096; in=W1; out=w1T; K=C_;  N=FF_; bx=r%128; by=r/128; }
    else                  { int r = tile-8192; in=W2; out=w2T; K=FF_; N=C_;  bx=r%32;  by=r/32;  }
    int k0 = by*32, n0 = bx*32;
    #pragma unroll
    for (int i = ty; i < 32; i += 8)
        t[i][tx] = in[(size_t)(k0+i)*N + n0 + tx];
    __syncthreads();
    #pragma unroll
    for (int i = ty; i < 32; i += 8)
        out[(size_t)(n0+i)*K + k0 + tx] = to_tf32(t[tx][i]);
}

// ------------------- layernorm (LN2, tf32-rounded output) -------------------
__global__ void __launch_bounds__(256) ln_kernel(const float* __restrict__ x,
                                                 const float* __restrict__ g,
                                                 const float* __restrict__ b,
                                                 float* __restrict__ out) {
    size_t row = blockIdx.x;
    const float* xr = x + row * C_;
    float v[4]; float s = 0.f;
    #pragma unroll
    for (int i = 0; i < 4; i++) { v[i] = xr[threadIdx.x + i*256]; s += v[i]; }
    float mu = block_reduce_sum(s) * (1.f / C_);
    float s2 = 0.f;
    #pragma unroll
    for (int i = 0; i < 4; i++) { float d = v[i] - mu; s2 += d * d; }
    float rstd = rsqrtf(block_reduce_sum(s2) * (1.f / C_) + 1e-5f);
    float* orow = out + row * C_;
    #pragma unroll
    for (int i = 0; i < 4; i++) {
        int j = threadIdx.x + i*256;
        orow[j] = to_tf32((v[i] - mu) * rstd * g[j] + b[j]);
    }
}

// ------------------- fused flash attention (identical to R13) ------------------
__global__ void __launch_bounds__(128, 2) flash_kernel(const float* __restrict__ qkv,
                                                       float* __restrict__ o) {
    extern __shared__ float sm[];
    float* Qs = sm;                  // [128][68]
    float* Ks = Qs + 128*68;         // [128][68]
    float* Vs = Ks + 128*68;         // [128][72]  row-major [key][d]

    int bh = blockIdx.y, bb = bh >> 4, hh = bh & 15;
    int q0 = blockIdx.x * 128;
    const float* qb = qkv + (size_t)(bb*T_ + q0)*S3_ + hh*DH_;
    const float* kb = qkv + (size_t)bb*T_*S3_ + C_   + hh*DH_;
    const float* vb = qkv + (size_t)bb*T_*S3_ + 2*C_ + hh*DH_;

    int tid = threadIdx.x, wid = tid >> 5, lane = tid & 31;
    int g = lane >> 2, tq = lane & 3;
    int wm0 = wid * 32;

    #pragma unroll
    for (int c = tid; c < 2048; c += 128) {
        int m = c >> 4, d4 = (c & 15) << 2;
        cp16(&Qs[m*68 + d4], qb + (size_t)m*S3_ + d4);
    }
    cp_commit();
    cp_wait<0>();
    __syncthreads();

    uint32_t qf[8][2][4];
    #pragma unroll
    for (int ks = 0; ks < 8; ks++) {
        int kk = ks * 8;
        #pragma unroll
        for (int mt = 0; mt < 2; mt++) {
            int mr = wm0 + mt*16;
            qf[ks][mt][0] = __float_as_uint(Qs[(mr+g  )*68 + kk + tq    ]);
            qf[ks][mt][1] = __float_as_uint(Qs[(mr+g+8)*68 + kk + tq    ]);
            qf[ks][mt][2] = __float_as_uint(Qs[(mr+g  )*68 + kk + tq + 4]);
            qf[ks][mt][3] = __float_as_uint(Qs[(mr+g+8)*68 + kk + tq + 4]);
        }
    }

    float lrow[2][2] = {{0.f,0.f},{0.f,0.f}};
    float acc_o[2][8][4];
    #pragma unroll
    for (int mt = 0; mt < 2; mt++)
        #pragma unroll
        for (int dt = 0; dt < 8; dt++)
            #pragma unroll
            for (int r = 0; r < 4; r++) acc_o[mt][dt][r] = 0.f;

    int src0 = (lane & ~3) | (tq >> 1);
    int src1 = src0 + 2;
    bool odd = (tq & 1);

    for (int n0 = 0; n0 < T_; n0 += 128) {
        __syncthreads();
        #pragma unroll
        for (int c = tid; c < 2048; c += 128) {
            int n = c >> 4, d4 = (c & 15) << 2;
            cp16(&Ks[n*68 + d4], kb + (size_t)(n0+n)*S3_ + d4);
        }
        #pragma unroll
        for (int c = tid; c < 2048; c += 128) {
            int n = c >> 4, d4 = (c & 15) << 2;
            cp16(&Vs[n*72 + d4], vb + (size_t)(n0+n)*S3_ + d4);
        }
        cp_commit();
        cp_wait<0>();
        __syncthreads();

        #pragma unroll
        for (int ch = 0; ch < 4; ch++) {
            int kbase = ch * 32;

            float s[2][4][4];
            #pragma unroll
            for (int mt = 0; mt < 2; mt++)
                #pragma unroll
                for (int nt = 0; nt < 4; nt++) {
                    s[mt][nt][0]=0.f; s[mt][nt][1]=0.f; s[mt][nt][2]=0.f; s[mt][nt][3]=0.f;
                }
            #pragma unroll
            for (int ks = 0; ks < 8; ks++) {
                int kk = ks * 8;
                #pragma unroll
                for (int nt = 0; nt < 4; nt++) {
                    uint32_t b[2];
                    b[0] = __float_as_uint(Ks[(kbase+nt*8+g)*68 + kk + tq    ]);
                    b[1] = __float_as_uint(Ks[(kbase+nt*8+g)*68 + kk + tq + 4]);
                    mma_tf32(s[0][nt], qf[ks][0], b);
                    mma_tf32(s[1][nt], qf[ks][1], b);
                }
            }

            #pragma unroll
            for (int ksg = 0; ksg < 4; ksg++) {
                uint32_t a[2][4];
                #pragma unroll
                for (int mt = 0; mt < 2; mt++) {
                    float p0 = exp2f(s[mt][ksg][0]*ESC);
                    float p1 = exp2f(s[mt][ksg][1]*ESC);
                    float p2 = exp2f(s[mt][ksg][2]*ESC);
                    float p3 = exp2f(s[mt][ksg][3]*ESC);
                    lrow[mt][0] += p0 + p1;
                    lrow[mt][1] += p2 + p3;
                    uint32_t u0 = tf32u(p0), u1 = tf32u(p1), u2 = tf32u(p2), u3 = tf32u(p3);
                    uint32_t w00 = __shfl_sync(0xffffffffu, u0, src0);
                    uint32_t w01 = __shfl_sync(0xffffffffu, u1, src0);
                    uint32_t w10 = __shfl_sync(0xffffffffu, u0, src1);
                    uint32_t w11 = __shfl_sync(0xffffffffu, u1, src1);
                    uint32_t x00 = __shfl_sync(0xffffffffu, u2, src0);
                    uint32_t x01 = __shfl_sync(0xffffffffu, u3, src0);
                    uint32_t x10 = __shfl_sync(0xffffffffu, u2, src1);
                    uint32_t x11 = __shfl_sync(0xffffffffu, u3, src1);
                    a[mt][0] = odd ? w01 : w00;
                    a[mt][2] = odd ? w11 : w10;
                    a[mt][1] = odd ? x01 : x00;
                    a[mt][3] = odd ? x11 : x10;
                }
                int kk = kbase + ksg*8;
                #pragma unroll
                for (int dt = 0; dt < 8; dt++) {
                    uint32_t b[2];
                    b[0] = __float_as_uint(Vs[(kk + tq    )*72 + dt*8 + g]);
                    b[1] = __float_as_uint(Vs[(kk + tq + 4)*72 + dt*8 + g]);
                    mma_tf32(acc_o[0][dt], a[0], b);
                    mma_tf32(acc_o[1][dt], a[1], b);
                }
            }
        }
    }

    #pragma unroll
    for (int mt = 0; mt < 2; mt++) {
        float l0 = lrow[mt][0], l1 = lrow[mt][1];
        l0 += __shfl_xor_sync(0xffffffffu, l0, 1);
        l0 += __shfl_xor_sync(0xffffffffu, l0, 2);
        l1 += __shfl_xor_sync(0xffffffffu, l1, 1);
        l1 += __shfl_xor_sync(0xffffffffu, l1, 2);
        float inv0 = 1.f / l0, inv1 = 1.f / l1;
        size_t r0 = (size_t)(bb*T_ + q0 + wm0 + mt*16 + g) * C_ + hh*DH_;
        size_t r1 = r0 + (size_t)8 * C_;
        #pragma unroll
        for (int dt = 0; dt < 8; dt++) {
            int col = dt*8 + 2*tq;
            o[r0 + col    ] = to_tf32(acc_o[mt][dt][0] * inv0);
            o[r0 + col + 1] = to_tf32(acc_o[mt][dt][1] * inv0);
            o[r1 + col    ] = to_tf32(acc_o[mt][dt][2] * inv1);
            o[r1 + col + 1] = to_tf32(acc_o[mt][dt][3] * inv1);
        }
    }
}

// ------------------- tf32 GEMM: 256 thr, 8 warps 32x64, BK=32, 2-stage ---------
// Halved warp tile -> 64 acc regs -> 2 CTAs x 8 warps = 16 warps/SM (latency cover).
__global__ void __launch_bounds__(256, 2)
mma_gemm(const float* __restrict__ A, int lda,
         const float* __restrict__ W, int K,
         float* __restrict__ C, int ldc,
         const float* __restrict__ bias,
         const float* __restrict__ resid, int relu, int round_out) {
    constexpr int ST = 36;
    constexpr int TS = 128*ST;
    extern __shared__ float smem[];
    float* As = smem;               // [2][128][36]
    float* Bs = smem + 2*TS;        // [2][128][36]

    int tid = threadIdx.x, wid = tid >> 5, lane = tid & 31;
    int g = lane >> 2, tq = lane & 3;
    int wm0 = (wid & 3) * 32;       // 4 warps along M
    int wn0 = (wid >> 2) * 64;      // 2 warps along N
    int row0 = blockIdx.y * 128, col0 = blockIdx.x * 128;

    auto stage = [&](int b, int kt) {
        float* Ab = As + b*TS;
        float* Bb = Bs + b*TS;
        int k0 = kt << 5;
        #pragma unroll
        for (int c = tid; c < 1024; c += 256) {
            int m = c >> 3, ch = c & 7;
            cp16(&Ab[m*ST + ch*4], A + (size_t)(row0 + m)*lda + k0 + ch*4);
        }
        #pragma unroll
        for (int c = tid; c < 1024; c += 256) {
            int n = c >> 3, ch = c & 7;
            cp16(&Bb[n*ST + ch*4], W + (size_t)(col0 + n)*K + k0 + ch*4);
        }
    };

    float acc[2][8][4];
    #pragma unroll
    for (int i = 0; i < 2; i++)
        #pragma unroll
        for (int j = 0; j < 8; j++)
            #pragma unroll
            for (int r = 0; r < 4; r++) acc[i][j][r] = 0.f;

    stage(0, 0); cp_commit();

    int NT = K >> 5;
    for (int kt = 0; kt < NT; kt++) {
        if (kt + 1 < NT) {
            stage((kt + 1) & 1, kt + 1);
            cp_commit();
            cp_wait<1>();
        } else {
            cp_wait<0>();
        }
        __syncthreads();

        const float* Ab = As + (kt & 1)*TS;
        const float* Bb = Bs + (kt & 1)*TS;
        #pragma unroll
        for (int ks = 0; ks < 4; ks++) {
            int kb = ks * 8;
            uint32_t a[2][4], b[8][2];
            #pragma unroll
            for (int mt = 0; mt < 2; mt++) {
                int mr = wm0 + mt*16;
                a[mt][0] = __float_as_uint(Ab[(mr + g    )*ST + kb + tq    ]);
                a[mt][1] = __float_as_uint(Ab[(mr + g + 8)*ST + kb + tq    ]);
                a[mt][2] = __float_as_uint(Ab[(mr + g    )*ST + kb + tq + 4]);
                a[mt][3] = __float_as_uint(Ab[(mr + g + 8)*ST + kb + tq + 4]);
            }
            #pragma unroll
            for (int nt = 0; nt < 8; nt++) {
                int nr = wn0 + nt*8 + g;
                b[nt][0] = __float_as_uint(Bb[nr*ST + kb + tq    ]);
                b[nt][1] = __float_as_uint(Bb[nr*ST + kb + tq + 4]);
            }
            #pragma unroll
            for (int mt = 0; mt < 2; mt++)
                #pragma unroll
                for (int nt = 0; nt < 8; nt++)
                    mma_tf32(acc[mt][nt], a[mt], b[nt]);
        }
        __syncthreads();
    }

    // ---- epilogue (float2 stores) ----
    #pragma unroll
    for (int mt = 0; mt < 2; mt++) {
        int m0 = row0 + wm0 + mt*16 + g;
        #pragma unroll
        for (int nt = 0; nt < 8; nt++) {
            int n = col0 + wn0 + nt*8 + 2*tq;
            float bx = 0.f, by = 0.f;
            if (bias) { bx = bias[n]; by = bias[n+1]; }
            #pragma unroll
            for (int half = 0; half < 2; half++) {
                int m = m0 + half*8;
                float vx = acc[mt][nt][half*2+0] + bx;
                float vy = acc[mt][nt][half*2+1] + by;
                size_t ci = (size_t)m * ldc + n;
                if (resid) {
                    float2 rr = *reinterpret_cast<const float2*>(&resid[ci]);
                    vx += rr.x; vy += rr.y;
                }
                if (relu) { vx = fmaxf(vx, 0.f); vy = fmaxf(vy, 0.f); }
                if (round_out) { vx = to_tf32(vx); vy = to_tf32(vy); }
                *reinterpret_cast<float2*>(&C[ci]) = make_float2(vx, vy);
            }
        }
    }
}

// ------------------- launcher ---------------------------------------------------
extern "C" void kernel_launch(void* const* d_in, const int* in_sizes, int n_in,
                              void* d_out, int out_size) {
    const float* x   = (const float*)d_in[0];
    const float* Wq  = (const float*)d_in[1];
    const float* Wk  = (const float*)d_in[2];
    const float* Wv  = (const float*)d_in[3];
    const float* Wo  = (const float*)d_in[4];
    const float* bo  = (const float*)d_in[5];
    const float* W1  = (const float*)d_in[6];
    const float* b1  = (const float*)d_in[7];
    const float* W2  = (const float*)d_in[8];
    const float* b2  = (const float*)d_in[9];
    const float* g1  = (const float*)d_in[10];
    const float* be1 = (const float*)d_in[11];
    const float* g2  = (const float*)d_in[12];
    const float* be2 = (const float*)d_in[13];
    float* out = (float*)d_out;

    float *h, *qkv, *o, *h2, *ff, *wqkvT, *woT, *w1T, *w2T;
    cudaGetSymbolAddress((void**)&h,     g_h);
    cudaGetSymbolAddress((void**)&qkv,   g_qkv);
    cudaGetSymbolAddress((void**)&o,     g_o);
    cudaGetSymbolAddress((void**)&h2,    g_h2);
    cudaGetSymbolAddress((void**)&ff,    g_ff);
    cudaGetSymbolAddress((void**)&wqkvT, g_WqkvT);
    cudaGetSymbolAddress((void**)&woT,   g_WoT);
    cudaGetSymbolAddress((void**)&w1T,   g_W1T);
    cudaGetSymbolAddress((void**)&w2T,   g_W2T);

    const int FLASH_SMEM = (128*68 + 128*68 + 128*72) * 4;   // 106496
    const int GEMM_SMEM  = 4 * 128 * 36 * 4;                 // 73728
    static int smem_set = 0;
    if (!smem_set) {
        cudaFuncSetAttribute(flash_kernel,
                             cudaFuncAttributeMaxDynamicSharedMemorySize, FLASH_SMEM);
        cudaFuncSetAttribute(mma_gemm,
                             cudaFuncAttributeMaxDynamicSharedMemorySize, GEMM_SMEM);
        smem_set = 1;
    }

    // merged weight prep + LN1
    prep_ln<<<12288 + BT_, 256>>>(Wq, Wk, Wv, Wo, W1, W2,
                                  wqkvT, woT, w1T, w2T, x, g1, be1, h);

    // qkv = h @ Wqkv
    mma_gemm<<<dim3(S3_/128, BT_/128), 256, GEMM_SMEM>>>(
        h, C_, wqkvT, C_, qkv, S3_, nullptr, nullptr, 0, 1);

    // fused attention -> o
    flash_kernel<<<dim3(T_/128, B_*H_), 128, FLASH_SMEM>>>(qkv, o);

    // x1 = x + o @ Wo + bo -> d_out
    mma_gemm<<<dim3(C_/128, BT_/128), 256, GEMM_SMEM>>>(
        o, C_, woT, C_, out, C_, bo, x, 0, 0);

    // LN2
    ln_kernel<<<BT_, 256>>>(out, g2, be2, h2);

    // ff = relu(h2 @ W1 + b1)
    mma_gemm<<<dim3(FF_/128, BT_/128), 256, GEMM_SMEM>>>(
        h2, C_, w1T, C_, ff, FF_, b1, nullptr, 1, 1);

    // out = x1 + ff @ W2 + b2
    mma_gemm<<<dim3(C_/128, BT_/128), 256, GEMM_SMEM>>>(
        ff, FF_, w2T, FF_, out, C_, b2, out, 0, 0);
}

// round 16
// speedup vs baseline: 1.0219x; 1.0219x over previous
#include <cuda_runtime.h>
#include <math.h>
#include <stdint.h>

#define B_  2
#define T_  2048
#define C_  1024
#define H_  16
#define DH_ 64
#define BT_ (B_*T_)
#define FF_ (4*C_)
#define S3_ (3*C_)
// exp2 scale: (C^-0.5) * log2(e) = (1/32)*1.4426950408889634
#define ESC 0.045084220027780106f

// ------------------- device scratch -------------------
__device__ float g_h    [BT_*C_];
__device__ float g_qkv  [(size_t)BT_*S3_];
__device__ float g_o    [BT_*C_];
__device__ float g_h2   [BT_*C_];
__device__ float g_ff   [(size_t)BT_*FF_];
__device__ float g_WqkvT[(size_t)S3_*C_];   // [N=3C][K=C]
__device__ float g_WoT  [(size_t)C_*C_];    // [N=C][K=C]
__device__ float g_W1T  [(size_t)FF_*C_];   // [N=FF][K=C]
__device__ float g_W2T  [(size_t)C_*FF_];   // [N=C][K=FF]

// ------------------- helpers -------------------
__device__ __forceinline__ float to_tf32(float x) {
    uint32_t u; asm("cvt.rna.tf32.f32 %0, %1;" : "=r"(u) : "f"(x));
    return __uint_as_float(u);
}
__device__ __forceinline__ uint32_t tf32u(float x) {
    uint32_t u; asm("cvt.rna.tf32.f32 %0, %1;" : "=r"(u) : "f"(x));
    return u;
}
__device__ __forceinline__ void mma_tf32(float* c, const uint32_t* a, const uint32_t* b) {
    asm volatile(
        "mma.sync.aligned.m16n8k8.row.col.f32.tf32.tf32.f32 "
        "{%0,%1,%2,%3}, {%4,%5,%6,%7}, {%8,%9}, {%0,%1,%2,%3};"
        : "+f"(c[0]), "+f"(c[1]), "+f"(c[2]), "+f"(c[3])
        : "r"(a[0]), "r"(a[1]), "r"(a[2]), "r"(a[3]), "r"(b[0]), "r"(b[1]));
}
__device__ __forceinline__ void ldsm4(uint32_t* r, uint32_t saddr) {
    asm volatile("ldmatrix.sync.aligned.m8n8.x4.shared.b16 {%0,%1,%2,%3}, [%4];"
        : "=r"(r[0]), "=r"(r[1]), "=r"(r[2]), "=r"(r[3]) : "r"(saddr));
}
__device__ __forceinline__ void cp16(void* sptr, const void* gptr) {
    uint32_t s = (uint32_t)__cvta_generic_to_shared(sptr);
    asm volatile("cp.async.ca.shared.global [%0], [%1], 16;" :: "r"(s), "l"(gptr));
}
__device__ __forceinline__ void cp_commit() { asm volatile("cp.async.commit_group;"); }
template<int N> __device__ __forceinline__ void cp_wait() {
    asm volatile("cp.async.wait_group %0;" :: "n"(N));
}

__device__ __forceinline__ float block_reduce_sum(float v) {
    __shared__ float sm[8];
    __shared__ float res;
    #pragma unroll
    for (int o = 16; o; o >>= 1) v += __shfl_xor_sync(0xffffffffu, v, o);
    if ((threadIdx.x & 31) == 0) sm[threadIdx.x >> 5] = v;
    __syncthreads();
    if (threadIdx.x < 32) {
        float t = (threadIdx.x < 8) ? sm[threadIdx.x] : 0.f;
        #pragma unroll
        for (int o = 4; o; o >>= 1) t += __shfl_xor_sync(0xffffffffu, t, o);
        if (threadIdx.x == 0) res = t;
    }
    __syncthreads();
    return res;
}

// ------------------- merged weight prep + LN1 (single launch) ------------------
__global__ void __launch_bounds__(256)
prep_ln(const float* __restrict__ Wq, const float* __restrict__ Wk,
        const float* __restrict__ Wv, const float* __restrict__ Wo,
        const float* __restrict__ W1, const float* __restrict__ W2,
        float* __restrict__ wqkvT, float* __restrict__ woT,
        float* __restrict__ w1T,   float* __restrict__ w2T,
        const float* __restrict__ x, const float* __restrict__ g1,
        const float* __restrict__ be1, float* __restrict__ h) {
    int tile = blockIdx.x;

    if (tile >= 12288) {                    // ---- LN1 row ----
        size_t row = tile - 12288;
        const float* xr = x + row * C_;
        float v[4]; float s = 0.f;
        #pragma unroll
        for (int i = 0; i < 4; i++) { v[i] = xr[threadIdx.x + i*256]; s += v[i]; }
        float mu = block_reduce_sum(s) * (1.f / C_);
        float s2 = 0.f;
        #pragma unroll
        for (int i = 0; i < 4; i++) { float d = v[i] - mu; s2 += d * d; }
        float rstd = rsqrtf(block_reduce_sum(s2) * (1.f / C_) + 1e-5f);
        float* orow = h + row * C_;
        #pragma unroll
        for (int i = 0; i < 4; i++) {
            int j = threadIdx.x + i*256;
            orow[j] = to_tf32((v[i] - mu) * rstd * g1[j] + be1[j]);
        }
        return;
    }

    __shared__ float t[32][33];
    int tx = threadIdx.x & 31, ty = threadIdx.x >> 5;

    if (tile < 3072) {                      // ---- qkv repack-transpose ----
        int bx = tile % 96, by = tile / 96;
        int k0 = by*32, n0 = bx*32;
        int n = n0 + tx;
        const float* W = (n < C_) ? Wq : ((n < 2*C_) ? Wk : Wv);
        int nn = n % C_;
        #pragma unroll
        for (int i = ty; i < 32; i += 8)
            t[i][tx] = W[((size_t)(nn/DH_)*C_ + (k0+i))*DH_ + (nn%DH_)];
        __syncthreads();
        #pragma unroll
        for (int i = ty; i < 32; i += 8)
            wqkvT[(size_t)(n0+i)*C_ + k0 + tx] = to_tf32(t[tx][i]);
        return;
    }
    const float* in; float* out; int K, N, bx, by;
    if (tile < 4096)      { int r = tile-3072; in=Wo; out=woT; K=C_;  N=C_;  bx=r%32;  by=r/32;  }
    else if (tile < 8192) { int r = tile-4096; in=W1; out=w1T; K=C_;  N=FF_; bx=r%128; by=r/128; }
    else                  { int r = tile-8192; in=W2; out=w2T; K=FF_; N=C_;  bx=r%32;  by=r/32;  }
    int k0 = by*32, n0 = bx*32;
    #pragma unroll
    for (int i = ty; i < 32; i += 8)
        t[i][tx] = in[(size_t)(k0+i)*N + n0 + tx];
    __syncthreads();
    #pragma unroll
    for (int i = ty; i < 32; i += 8)
        out[(size_t)(n0+i)*K + k0 + tx] = to_tf32(t[tx][i]);
}

// ------------------- layernorm (LN2, tf32-rounded output) -------------------
__global__ void __launch_bounds__(256) ln_kernel(const float* __restrict__ x,
                                                 const float* __restrict__ g,
                                                 const float* __restrict__ b,
                                                 float* __restrict__ out) {
    size_t row = blockIdx.x;
    const float* xr = x + row * C_;
    float v[4]; float s = 0.f;
    #pragma unroll
    for (int i = 0; i < 4; i++) { v[i] = xr[threadIdx.x + i*256]; s += v[i]; }
    float mu = block_reduce_sum(s) * (1.f / C_);
    float s2 = 0.f;
    #pragma unroll
    for (int i = 0; i < 4; i++) { float d = v[i] - mu; s2 += d * d; }
    float rstd = rsqrtf(block_reduce_sum(s2) * (1.f / C_) + 1e-5f);
    float* orow = out + row * C_;
    #pragma unroll
    for (int i = 0; i < 4; i++) {
        int j = threadIdx.x + i*256;
        orow[j] = to_tf32((v[i] - mu) * rstd * g[j] + b[j]);
    }
}

// ------------------- fused flash attention (identical to R13) ------------------
__global__ void __launch_bounds__(128, 2) flash_kernel(const float* __restrict__ qkv,
                                                       float* __restrict__ o) {
    extern __shared__ float sm[];
    float* Qs = sm;                  // [128][68]
    float* Ks = Qs + 128*68;         // [128][68]
    float* Vs = Ks + 128*68;         // [128][72]  row-major [key][d]

    int bh = blockIdx.y, bb = bh >> 4, hh = bh & 15;
    int q0 = blockIdx.x * 128;
    const float* qb = qkv + (size_t)(bb*T_ + q0)*S3_ + hh*DH_;
    const float* kb = qkv + (size_t)bb*T_*S3_ + C_   + hh*DH_;
    const float* vb = qkv + (size_t)bb*T_*S3_ + 2*C_ + hh*DH_;

    int tid = threadIdx.x, wid = tid >> 5, lane = tid & 31;
    int g = lane >> 2, tq = lane & 3;
    int wm0 = wid * 32;

    #pragma unroll
    for (int c = tid; c < 2048; c += 128) {
        int m = c >> 4, d4 = (c & 15) << 2;
        cp16(&Qs[m*68 + d4], qb + (size_t)m*S3_ + d4);
    }
    cp_commit();
    cp_wait<0>();
    __syncthreads();

    uint32_t qf[8][2][4];
    #pragma unroll
    for (int ks = 0; ks < 8; ks++) {
        int kk = ks * 8;
        #pragma unroll
        for (int mt = 0; mt < 2; mt++) {
            int mr = wm0 + mt*16;
            qf[ks][mt][0] = __float_as_uint(Qs[(mr+g  )*68 + kk + tq    ]);
            qf[ks][mt][1] = __float_as_uint(Qs[(mr+g+8)*68 + kk + tq    ]);
            qf[ks][mt][2] = __float_as_uint(Qs[(mr+g  )*68 + kk + tq + 4]);
            qf[ks][mt][3] = __float_as_uint(Qs[(mr+g+8)*68 + kk + tq + 4]);
        }
    }

    float lrow[2][2] = {{0.f,0.f},{0.f,0.f}};
    float acc_o[2][8][4];
    #pragma unroll
    for (int mt = 0; mt < 2; mt++)
        #pragma unroll
        for (int dt = 0; dt < 8; dt++)
            #pragma unroll
            for (int r = 0; r < 4; r++) acc_o[mt][dt][r] = 0.f;

    int src0 = (lane & ~3) | (tq >> 1);
    int src1 = src0 + 2;
    bool odd = (tq & 1);

    for (int n0 = 0; n0 < T_; n0 += 128) {
        __syncthreads();
        #pragma unroll
        for (int c = tid; c < 2048; c += 128) {
            int n = c >> 4, d4 = (c & 15) << 2;
            cp16(&Ks[n*68 + d4], kb + (size_t)(n0+n)*S3_ + d4);
        }
        #pragma unroll
        for (int c = tid; c < 2048; c += 128) {
            int n = c >> 4, d4 = (c & 15) << 2;
            cp16(&Vs[n*72 + d4], vb + (size_t)(n0+n)*S3_ + d4);
        }
        cp_commit();
        cp_wait<0>();
        __syncthreads();

        #pragma unroll
        for (int ch = 0; ch < 4; ch++) {
            int kbase = ch * 32;

            float s[2][4][4];
            #pragma unroll
            for (int mt = 0; mt < 2; mt++)
                #pragma unroll
                for (int nt = 0; nt < 4; nt++) {
                    s[mt][nt][0]=0.f; s[mt][nt][1]=0.f; s[mt][nt][2]=0.f; s[mt][nt][3]=0.f;
                }
            #pragma unroll
            for (int ks = 0; ks < 8; ks++) {
                int kk = ks * 8;
                #pragma unroll
                for (int nt = 0; nt < 4; nt++) {
                    uint32_t b[2];
                    b[0] = __float_as_uint(Ks[(kbase+nt*8+g)*68 + kk + tq    ]);
                    b[1] = __float_as_uint(Ks[(kbase+nt*8+g)*68 + kk + tq + 4]);
                    mma_tf32(s[0][nt], qf[ks][0], b);
                    mma_tf32(s[1][nt], qf[ks][1], b);
                }
            }

            #pragma unroll
            for (int ksg = 0; ksg < 4; ksg++) {
                uint32_t a[2][4];
                #pragma unroll
                for (int mt = 0; mt < 2; mt++) {
                    float p0 = exp2f(s[mt][ksg][0]*ESC);
                    float p1 = exp2f(s[mt][ksg][1]*ESC);
                    float p2 = exp2f(s[mt][ksg][2]*ESC);
                    float p3 = exp2f(s[mt][ksg][3]*ESC);
                    lrow[mt][0] += p0 + p1;
                    lrow[mt][1] += p2 + p3;
                    uint32_t u0 = tf32u(p0), u1 = tf32u(p1), u2 = tf32u(p2), u3 = tf32u(p3);
                    uint32_t w00 = __shfl_sync(0xffffffffu, u0, src0);
                    uint32_t w01 = __shfl_sync(0xffffffffu, u1, src0);
                    uint32_t w10 = __shfl_sync(0xffffffffu, u0, src1);
                    uint32_t w11 = __shfl_sync(0xffffffffu, u1, src1);
                    uint32_t x00 = __shfl_sync(0xffffffffu, u2, src0);
                    uint32_t x01 = __shfl_sync(0xffffffffu, u3, src0);
                    uint32_t x10 = __shfl_sync(0xffffffffu, u2, src1);
                    uint32_t x11 = __shfl_sync(0xffffffffu, u3, src1);
                    a[mt][0] = odd ? w01 : w00;
                    a[mt][2] = odd ? w11 : w10;
                    a[mt][1] = odd ? x01 : x00;
                    a[mt][3] = odd ? x11 : x10;
                }
                int kk = kbase + ksg*8;
                #pragma unroll
                for (int dt = 0; dt < 8; dt++) {
                    uint32_t b[2];
                    b[0] = __float_as_uint(Vs[(kk + tq    )*72 + dt*8 + g]);
                    b[1] = __float_as_uint(Vs[(kk + tq + 4)*72 + dt*8 + g]);
                    mma_tf32(acc_o[0][dt], a[0], b);
                    mma_tf32(acc_o[1][dt], a[1], b);
                }
            }
        }
    }

    #pragma unroll
    for (int mt = 0; mt < 2; mt++) {
        float l0 = lrow[mt][0], l1 = lrow[mt][1];
        l0 += __shfl_xor_sync(0xffffffffu, l0, 1);
        l0 += __shfl_xor_sync(0xffffffffu, l0, 2);
        l1 += __shfl_xor_sync(0xffffffffu, l1, 1);
        l1 += __shfl_xor_sync(0xffffffffu, l1, 2);
        float inv0 = 1.f / l0, inv1 = 1.f / l1;
        size_t r0 = (size_t)(bb*T_ + q0 + wm0 + mt*16 + g) * C_ + hh*DH_;
        size_t r1 = r0 + (size_t)8 * C_;
        #pragma unroll
        for (int dt = 0; dt < 8; dt++) {
            int col = dt*8 + 2*tq;
            o[r0 + col    ] = to_tf32(acc_o[mt][dt][0] * inv0);
            o[r0 + col + 1] = to_tf32(acc_o[mt][dt][1] * inv0);
            o[r1 + col    ] = to_tf32(acc_o[mt][dt][2] * inv1);
            o[r1 + col + 1] = to_tf32(acc_o[mt][dt][3] * inv1);
        }
    }
}

// ------------------- tf32 GEMM: 4 warps 64x64, BK=32, ldmatrix fragments -------
// A [M][K] row-major tf32; W [N][K] row-major tf32. Fragment loads via LDSM.x4:
// 16 scalar LDS -> 1 ldmatrix (conflict-free with ST=36).
__global__ void __launch_bounds__(128)
mma_gemm(const float* __restrict__ A, int lda,
         const float* __restrict__ W, int K,
         float* __restrict__ C, int ldc,
         const float* __restrict__ bias,
         const float* __restrict__ resid, int relu, int round_out) {
    constexpr int ST = 36;
    constexpr int TS = 128*ST;
    extern __shared__ float smem[];
    float* As = smem;               // [2][128][36]
    float* Bs = smem + 2*TS;        // [2][128][36]

    int tid = threadIdx.x, wid = tid >> 5, lane = tid & 31;
    int g = lane >> 2, tq = lane & 3;
    int wm0 = (wid & 1) * 64;
    int wn0 = (wid >> 1) * 64;
    int row0 = blockIdx.y * 128, col0 = blockIdx.x * 128;

    uint32_t sbase = (uint32_t)__cvta_generic_to_shared(smem);
    // ldmatrix lane-address offsets (in floats)
    int mi = lane >> 3, r8 = lane & 7;
    int aoff = (wm0 + (mi & 1)*8 + r8)*ST + (mi >> 1)*4;   // A: {+0/+8 rows} x {+0/+4 cols}
    int boff = (wn0 + (mi >> 1)*8 + r8)*ST + (mi & 1)*4;   // B: {+0/+4 cols} x {+0/+8 rows}

    auto stage = [&](int b, int kt) {
        float* Ab = As + b*TS;
        float* Bb = Bs + b*TS;
        int k0 = kt << 5;
        #pragma unroll
        for (int c = tid; c < 1024; c += 128) {
            int m = c >> 3, ch = c & 7;
            cp16(&Ab[m*ST + ch*4], A + (size_t)(row0 + m)*lda + k0 + ch*4);
        }
        #pragma unroll
        for (int c = tid; c < 1024; c += 128) {
            int n = c >> 3, ch = c & 7;
            cp16(&Bb[n*ST + ch*4], W + (size_t)(col0 + n)*K + k0 + ch*4);
        }
    };

    float acc[4][8][4];
    #pragma unroll
    for (int i = 0; i < 4; i++)
        #pragma unroll
        for (int j = 0; j < 8; j++)
            #pragma unroll
            for (int r = 0; r < 4; r++) acc[i][j][r] = 0.f;

    stage(0, 0); cp_commit();

    int NT = K >> 5;
    for (int kt = 0; kt < NT; kt++) {
        if (kt + 1 < NT) {
            stage((kt + 1) & 1, kt + 1);
            cp_commit();
            cp_wait<1>();
        } else {
            cp_wait<0>();
        }
        __syncthreads();

        uint32_t abase = sbase + ((kt & 1)*TS + aoff)*4;
        uint32_t bbase = sbase + (2*TS + (kt & 1)*TS + boff)*4;
        #pragma unroll
        for (int ks = 0; ks < 4; ks++) {
            int kb = ks * 8;
            uint32_t a[4][4], bq[4][4];
            #pragma unroll
            for (int mt = 0; mt < 4; mt++)
                ldsm4(a[mt], abase + (mt*16*ST + kb)*4);
            #pragma unroll
            for (int p = 0; p < 4; p++)
                ldsm4(bq[p], bbase + (p*16*ST + kb)*4);
            #pragma unroll
            for (int mt = 0; mt < 4; mt++)
                #pragma unroll
                for (int nt = 0; nt < 8; nt++)
                    mma_tf32(acc[mt][nt], a[mt], &bq[nt >> 1][(nt & 1)*2]);
        }
        __syncthreads();
    }

    // ---- epilogue (float2 stores) ----
    #pragma unroll
    for (int mt = 0; mt < 4; mt++) {
        int m0 = row0 + wm0 + mt*16 + g;
        #pragma unroll
        for (int nt = 0; nt < 8; nt++) {
            int n = col0 + wn0 + nt*8 + 2*tq;
            float bx = 0.f, by = 0.f;
            if (bias) { bx = bias[n]; by = bias[n+1]; }
            #pragma unroll
            for (int half = 0; half < 2; half++) {
                int m = m0 + half*8;
                float vx = acc[mt][nt][half*2+0] + bx;
                float vy = acc[mt][nt][half*2+1] + by;
                size_t ci = (size_t)m * ldc + n;
                if (resid) {
                    float2 rr = *reinterpret_cast<const float2*>(&resid[ci]);
                    vx += rr.x; vy += rr.y;
                }
                if (relu) { vx = fmaxf(vx, 0.f); vy = fmaxf(vy, 0.f); }
                if (round_out) { vx = to_tf32(vx); vy = to_tf32(vy); }
                *reinterpret_cast<float2*>(&C[ci]) = make_float2(vx, vy);
            }
        }
    }
}

// ------------------- launcher ---------------------------------------------------
extern "C" void kernel_launch(void* const* d_in, const int* in_sizes, int n_in,
                              void* d_out, int out_size) {
    const float* x   = (const float*)d_in[0];
    const float* Wq  = (const float*)d_in[1];
    const float* Wk  = (const float*)d_in[2];
    const float* Wv  = (const float*)d_in[3];
    const float* Wo  = (const float*)d_in[4];
    const float* bo  = (const float*)d_in[5];
    const float* W1  = (const float*)d_in[6];
    const float* b1  = (const float*)d_in[7];
    const float* W2  = (const float*)d_in[8];
    const float* b2  = (const float*)d_in[9];
    const float* g1  = (const float*)d_in[10];
    const float* be1 = (const float*)d_in[11];
    const float* g2  = (const float*)d_in[12];
    const float* be2 = (const float*)d_in[13];
    float* out = (float*)d_out;

    float *h, *qkv, *o, *h2, *ff, *wqkvT, *woT, *w1T, *w2T;
    cudaGetSymbolAddress((void**)&h,     g_h);
    cudaGetSymbolAddress((void**)&qkv,   g_qkv);
    cudaGetSymbolAddress((void**)&o,     g_o);
    cudaGetSymbolAddress((void**)&h2,    g_h2);
    cudaGetSymbolAddress((void**)&ff,    g_ff);
    cudaGetSymbolAddress((void**)&wqkvT, g_WqkvT);
    cudaGetSymbolAddress((void**)&woT,   g_WoT);
    cudaGetSymbolAddress((void**)&w1T,   g_W1T);
    cudaGetSymbolAddress((void**)&w2T,   g_W2T);

    const int FLASH_SMEM = (128*68 + 128*68 + 128*72) * 4;   // 106496
    const int GEMM_SMEM  = 4 * 128 * 36 * 4;                 // 73728
    static int smem_set = 0;
    if (!smem_set) {
        cudaFuncSetAttribute(flash_kernel,
                             cudaFuncAttributeMaxDynamicSharedMemorySize, FLASH_SMEM);
        cudaFuncSetAttribute(mma_gemm,
                             cudaFuncAttributeMaxDynamicSharedMemorySize, GEMM_SMEM);
        smem_set = 1;
    }

    // merged weight prep + LN1
    prep_ln<<<12288 + BT_, 256>>>(Wq, Wk, Wv, Wo, W1, W2,
                                  wqkvT, woT, w1T, w2T, x, g1, be1, h);

    // qkv = h @ Wqkv
    mma_gemm<<<dim3(S3_/128, BT_/128), 128, GEMM_SMEM>>>(
        h, C_, wqkvT, C_, qkv, S3_, nullptr, nullptr, 0, 1);

    // fused attention -> o
    flash_kernel<<<dim3(T_/128, B_*H_), 128, FLASH_SMEM>>>(qkv, o);

    // x1 = x + o @ Wo + bo -> d_out
    mma_gemm<<<dim3(C_/128, BT_/128), 128, GEMM_SMEM>>>(
        o, C_, woT, C_, out, C_, bo, x, 0, 0);

    // LN2
    ln_kernel<<<BT_, 256>>>(out, g2, be2, h2);

    // ff = relu(h2 @ W1 + b1)
    mma_gemm<<<dim3(FF_/128, BT_/128), 128, GEMM_SMEM>>>(
        h2, C_, w1T, C_, ff, FF_, b1, nullptr, 1, 1);

    // out = x1 + ff @ W2 + b2
    mma_gemm<<<dim3(C_/128, BT_/128), 128, GEMM_SMEM>>>(
        ff, FF_, w2T, FF_, out, C_, b2, out, 0, 0);
}

// round 17
// speedup vs baseline: 1.7699x; 1.7319x over previous
#include <cuda_runtime.h>
#include <cuda_fp16.h>
#include <math.h>
#include <stdint.h>

#define B_  2
#define T_  2048
#define C_  1024
#define H_  16
#define DH_ 64
#define BT_ (B_*T_)
#define FF_ (4*C_)
#define S3_ (3*C_)
// exp2 scale: (C^-0.5) * log2(e)
#define ESC 0.045084220027780106f

// ------------------- device scratch (fp16 activations/weights) -----------------
__device__ __half g_h    [BT_*C_];
__device__ __half g_qkv  [(size_t)BT_*S3_];
__device__ __half g_o    [BT_*C_];
__device__ __half g_h2   [BT_*C_];
__device__ __half g_ff   [(size_t)BT_*FF_];
__device__ __half g_WqkvT[(size_t)S3_*C_];   // [N=3C][K=C]
__device__ __half g_WoT  [(size_t)C_*C_];    // [N=C][K=C]
__device__ __half g_W1T  [(size_t)FF_*C_];   // [N=FF][K=C]
__device__ __half g_W2T  [(size_t)C_*FF_];   // [N=C][K=FF]

// ------------------- helpers -------------------
__device__ __forceinline__ uint32_t h2pack(float lo, float hi) {
    uint32_t d; asm("cvt.rn.f16x2.f32 %0, %1, %2;" : "=r"(d) : "f"(hi), "f"(lo));
    return d;
}
__device__ __forceinline__ void mma_f16(float* c, const uint32_t* a, const uint32_t* b) {
    asm volatile(
        "mma.sync.aligned.m16n8k16.row.col.f32.f16.f16.f32 "
        "{%0,%1,%2,%3}, {%4,%5,%6,%7}, {%8,%9}, {%0,%1,%2,%3};"
        : "+f"(c[0]), "+f"(c[1]), "+f"(c[2]), "+f"(c[3])
        : "r"(a[0]), "r"(a[1]), "r"(a[2]), "r"(a[3]), "r"(b[0]), "r"(b[1]));
}
__device__ __forceinline__ void ldsm4(uint32_t* r, uint32_t saddr) {
    asm volatile("ldmatrix.sync.aligned.m8n8.x4.shared.b16 {%0,%1,%2,%3}, [%4];"
        : "=r"(r[0]), "=r"(r[1]), "=r"(r[2]), "=r"(r[3]) : "r"(saddr));
}
__device__ __forceinline__ void ldsm4t(uint32_t* r, uint32_t saddr) {
    asm volatile("ldmatrix.sync.aligned.m8n8.x4.trans.shared.b16 {%0,%1,%2,%3}, [%4];"
        : "=r"(r[0]), "=r"(r[1]), "=r"(r[2]), "=r"(r[3]) : "r"(saddr));
}
__device__ __forceinline__ void cp16(void* sptr, const void* gptr) {
    uint32_t s = (uint32_t)__cvta_generic_to_shared(sptr);
    asm volatile("cp.async.ca.shared.global [%0], [%1], 16;" :: "r"(s), "l"(gptr));
}
__device__ __forceinline__ void cp_commit() { asm volatile("cp.async.commit_group;"); }
template<int N> __device__ __forceinline__ void cp_wait() {
    asm volatile("cp.async.wait_group %0;" :: "n"(N));
}

__device__ __forceinline__ float block_reduce_sum(float v) {
    __shared__ float sm[8];
    __shared__ float res;
    #pragma unroll
    for (int o = 16; o; o >>= 1) v += __shfl_xor_sync(0xffffffffu, v, o);
    if ((threadIdx.x & 31) == 0) sm[threadIdx.x >> 5] = v;
    __syncthreads();
    if (threadIdx.x < 32) {
        float t = (threadIdx.x < 8) ? sm[threadIdx.x] : 0.f;
        #pragma unroll
        for (int o = 4; o; o >>= 1) t += __shfl_xor_sync(0xffffffffu, t, o);
        if (threadIdx.x == 0) res = t;
    }
    __syncthreads();
    return res;
}

// ------------------- merged weight prep + LN1 (fp16 outputs) -------------------
__global__ void __launch_bounds__(256)
prep_ln(const float* __restrict__ Wq, const float* __restrict__ Wk,
        const float* __restrict__ Wv, const float* __restrict__ Wo,
        const float* __restrict__ W1, const float* __restrict__ W2,
        __half* __restrict__ wqkvT, __half* __restrict__ woT,
        __half* __restrict__ w1T,   __half* __restrict__ w2T,
        const float* __restrict__ x, const float* __restrict__ g1,
        const float* __restrict__ be1, __half* __restrict__ h) {
    int tile = blockIdx.x;

    if (tile >= 12288) {                    // ---- LN1 row ----
        size_t row = tile - 12288;
        const float* xr = x + row * C_;
        float v[4]; float s = 0.f;
        #pragma unroll
        for (int i = 0; i < 4; i++) { v[i] = xr[threadIdx.x + i*256]; s += v[i]; }
        float mu = block_reduce_sum(s) * (1.f / C_);
        float s2 = 0.f;
        #pragma unroll
        for (int i = 0; i < 4; i++) { float d = v[i] - mu; s2 += d * d; }
        float rstd = rsqrtf(block_reduce_sum(s2) * (1.f / C_) + 1e-5f);
        __half* orow = h + row * C_;
        #pragma unroll
        for (int i = 0; i < 4; i++) {
            int j = threadIdx.x + i*256;
            orow[j] = __float2half((v[i] - mu) * rstd * g1[j] + be1[j]);
        }
        return;
    }

    __shared__ float t[32][33];
    int tx = threadIdx.x & 31, ty = threadIdx.x >> 5;

    if (tile < 3072) {                      // ---- qkv repack-transpose ----
        int bx = tile % 96, by = tile / 96;
        int k0 = by*32, n0 = bx*32;
        int n = n0 + tx;
        const float* W = (n < C_) ? Wq : ((n < 2*C_) ? Wk : Wv);
        int nn = n % C_;
        #pragma unroll
        for (int i = ty; i < 32; i += 8)
            t[i][tx] = W[((size_t)(nn/DH_)*C_ + (k0+i))*DH_ + (nn%DH_)];
        __syncthreads();
        #pragma unroll
        for (int i = ty; i < 32; i += 8)
            wqkvT[(size_t)(n0+i)*C_ + k0 + tx] = __float2half(t[tx][i]);
        return;
    }
    const float* in; __half* out; int K, N, bx, by;
    if (tile < 4096)      { int r = tile-3072; in=Wo; out=woT; K=C_;  N=C_;  bx=r%32;  by=r/32;  }
    else if (tile < 8192) { int r = tile-4096; in=W1; out=w1T; K=C_;  N=FF_; bx=r%128; by=r/128; }
    else                  { int r = tile-8192; in=W2; out=w2T; K=FF_; N=C_;  bx=r%32;  by=r/32;  }
    int k0 = by*32, n0 = bx*32;
    #pragma unroll
    for (int i = ty; i < 32; i += 8)
        t[i][tx] = in[(size_t)(k0+i)*N + n0 + tx];
    __syncthreads();
    #pragma unroll
    for (int i = ty; i < 32; i += 8)
        out[(size_t)(n0+i)*K + k0 + tx] = __float2half(t[tx][i]);
}

// ------------------- layernorm (LN2, fp16 output) -------------------
__global__ void __launch_bounds__(256) ln_kernel(const float* __restrict__ x,
                                                 const float* __restrict__ g,
                                                 const float* __restrict__ b,
                                                 __half* __restrict__ out) {
    size_t row = blockIdx.x;
    const float* xr = x + row * C_;
    float v[4]; float s = 0.f;
    #pragma unroll
    for (int i = 0; i < 4; i++) { v[i] = xr[threadIdx.x + i*256]; s += v[i]; }
    float mu = block_reduce_sum(s) * (1.f / C_);
    float s2 = 0.f;
    #pragma unroll
    for (int i = 0; i < 4; i++) { float d = v[i] - mu; s2 += d * d; }
    float rstd = rsqrtf(block_reduce_sum(s2) * (1.f / C_) + 1e-5f);
    __half* orow = out + row * C_;
    #pragma unroll
    for (int i = 0; i < 4; i++) {
        int j = threadIdx.x + i*256;
        orow[j] = __float2half((v[i] - mu) * rstd * g[j] + b[j]);
    }
}

// ------------------- fused flash attention, fp16 mma (k16) ---------------------
// 4 warps x 32 q-rows. Q frags hoisted; PV A-frags come straight from exp(S)
// accumulator pairs (no shuffles); V B-frags via ldmatrix.trans.
__global__ void __launch_bounds__(128, 2) flash_kernel(const __half* __restrict__ qkv,
                                                       __half* __restrict__ o) {
    constexpr int STF = 72;                 // halves per row (conflict-free ldsm)
    extern __shared__ __half smh[];
    __half* Qs = smh;                       // [128][72]
    __half* Ks = Qs + 128*STF;              // [128][72]
    __half* Vs = Ks + 128*STF;              // [128][72] row-major [key][d]
    const int KOFF = 128*STF, VOFF = 2*128*STF;

    int bh = blockIdx.y, bb = bh >> 4, hh = bh & 15;
    int q0 = blockIdx.x * 128;
    const __half* qb = qkv + (size_t)(bb*T_ + q0)*S3_ + hh*DH_;
    const __half* kb = qkv + (size_t)bb*T_*S3_ + C_   + hh*DH_;
    const __half* vb = qkv + (size_t)bb*T_*S3_ + 2*C_ + hh*DH_;

    int tid = threadIdx.x, wid = tid >> 5, lane = tid & 31;
    int g = lane >> 2, tq = lane & 3;
    int wm0 = wid * 32;
    int mi = lane >> 3, r8 = lane & 7;

    uint32_t sbase = (uint32_t)__cvta_generic_to_shared(smh);
    // lane offsets (halves) for ldsm matrices
    int qaoff = ((mi & 1)*8 + r8)*STF + (mi >> 1)*8;   // A: rows{+0,+8} x k{0,8}
    int kboff = ((mi >> 1)*8 + r8)*STF + (mi & 1)*8;   // B: n{+0,+8} x k{0,8}
    int voff  = ((mi & 1)*8 + r8)*STF + (mi >> 1)*8;   // V(trans): keys{+0,+8} x d{0,8}

    // stage Q (64 halves/row = 8 cp16 chunks)
    #pragma unroll
    for (int c = tid; c < 1024; c += 128) {
        int m = c >> 3, ch = c & 7;
        cp16(&Qs[m*STF + ch*8], qb + (size_t)m*S3_ + ch*8);
    }
    cp_commit();
    cp_wait<0>();
    __syncthreads();

    // hoist Q fragments: 4 k16 steps x 2 mtiles
    uint32_t qf[4][2][4];
    #pragma unroll
    for (int ks = 0; ks < 4; ks++)
        #pragma unroll
        for (int mt = 0; mt < 2; mt++)
            ldsm4(qf[ks][mt], sbase + (uint32_t)(((wm0 + mt*16)*STF) + qaoff + ks*16)*2);

    float lrow[2][2] = {{0.f,0.f},{0.f,0.f}};
    float acc_o[2][8][4];
    #pragma unroll
    for (int mt = 0; mt < 2; mt++)
        #pragma unroll
        for (int dt = 0; dt < 8; dt++)
            #pragma unroll
            for (int r = 0; r < 4; r++) acc_o[mt][dt][r] = 0.f;

    uint32_t kbbase = sbase + (uint32_t)(KOFF + kboff)*2;
    uint32_t vbbase = sbase + (uint32_t)(VOFF + voff)*2;

    for (int n0 = 0; n0 < T_; n0 += 128) {
        __syncthreads();
        #pragma unroll
        for (int c = tid; c < 1024; c += 128) {
            int n = c >> 3, ch = c & 7;
            cp16(&Ks[n*STF + ch*8], kb + (size_t)(n0+n)*S3_ + ch*8);
        }
        #pragma unroll
        for (int c = tid; c < 1024; c += 128) {
            int n = c >> 3, ch = c & 7;
            cp16(&Vs[n*STF + ch*8], vb + (size_t)(n0+n)*S3_ + ch*8);
        }
        cp_commit();
        cp_wait<0>();
        __syncthreads();

        #pragma unroll
        for (int chk = 0; chk < 4; chk++) {
            int kbase = chk * 32;

            // ---- S = Q K^T over 32 keys ----
            float s[2][4][4];
            #pragma unroll
            for (int mt = 0; mt < 2; mt++)
                #pragma unroll
                for (int nt = 0; nt < 4; nt++) {
                    s[mt][nt][0]=0.f; s[mt][nt][1]=0.f; s[mt][nt][2]=0.f; s[mt][nt][3]=0.f;
                }
            #pragma unroll
            for (int ks = 0; ks < 4; ks++) {
                uint32_t kq[2][4];
                #pragma unroll
                for (int p = 0; p < 2; p++)
                    ldsm4(kq[p], kbbase + (uint32_t)(((kbase + p*16)*STF) + ks*16)*2);
                #pragma unroll
                for (int mt = 0; mt < 2; mt++)
                    #pragma unroll
                    for (int nt = 0; nt < 4; nt++)
                        mma_f16(s[mt][nt], qf[ks][mt], &kq[nt >> 1][(nt & 1)*2]);
            }

            // ---- P = exp(S/32); O += P V  (A-frags direct from S pairs) ----
            #pragma unroll
            for (int j = 0; j < 2; j++) {
                uint32_t a[2][4];
                #pragma unroll
                for (int mt = 0; mt < 2; mt++) {
                    float e0 = exp2f(s[mt][2*j  ][0]*ESC);
                    float e1 = exp2f(s[mt][2*j  ][1]*ESC);
                    float e2 = exp2f(s[mt][2*j  ][2]*ESC);
                    float e3 = exp2f(s[mt][2*j  ][3]*ESC);
                    float f0 = exp2f(s[mt][2*j+1][0]*ESC);
                    float f1 = exp2f(s[mt][2*j+1][1]*ESC);
                    float f2 = exp2f(s[mt][2*j+1][2]*ESC);
                    float f3 = exp2f(s[mt][2*j+1][3]*ESC);
                    lrow[mt][0] += e0 + e1 + f0 + f1;
                    lrow[mt][1] += e2 + e3 + f2 + f3;
                    a[mt][0] = h2pack(e0, e1);
                    a[mt][1] = h2pack(e2, e3);
                    a[mt][2] = h2pack(f0, f1);
                    a[mt][3] = h2pack(f2, f3);
                }
                uint32_t vq[4][4];
                #pragma unroll
                for (int dp = 0; dp < 4; dp++)
                    ldsm4t(vq[dp], vbbase + (uint32_t)(((kbase + j*16)*STF) + dp*16)*2);
                #pragma unroll
                for (int mt = 0; mt < 2; mt++)
                    #pragma unroll
                    for (int dt = 0; dt < 8; dt++)
                        mma_f16(acc_o[mt][dt], a[mt], &vq[dt >> 1][(dt & 1)*2]);
            }
        }
    }

    #pragma unroll
    for (int mt = 0; mt < 2; mt++) {
        float l0 = lrow[mt][0], l1 = lrow[mt][1];
        l0 += __shfl_xor_sync(0xffffffffu, l0, 1);
        l0 += __shfl_xor_sync(0xffffffffu, l0, 2);
        l1 += __shfl_xor_sync(0xffffffffu, l1, 1);
        l1 += __shfl_xor_sync(0xffffffffu, l1, 2);
        float inv0 = 1.f / l0, inv1 = 1.f / l1;
        size_t r0 = (size_t)(bb*T_ + q0 + wm0 + mt*16 + g) * C_ + hh*DH_;
        size_t r1 = r0 + (size_t)8 * C_;
        #pragma unroll
        for (int dt = 0; dt < 8; dt++) {
            int col = dt*8 + 2*tq;
            *reinterpret_cast<uint32_t*>(&o[r0 + col]) =
                h2pack(acc_o[mt][dt][0]*inv0, acc_o[mt][dt][1]*inv0);
            *reinterpret_cast<uint32_t*>(&o[r1 + col]) =
                h2pack(acc_o[mt][dt][2]*inv1, acc_o[mt][dt][3]*inv1);
        }
    }
}

// ------------------- fp16 GEMM: 4 warps 64x64, BK=32, k16 mma, ldmatrix --------
// A [M][K] half row-major; W [N][K] half. Out: Cf (fp32 +bias/resid) or Ch (half +bias/relu).
__global__ void __launch_bounds__(128)
mma_gemm(const __half* __restrict__ A, int lda,
         const __half* __restrict__ W, int K,
         float* __restrict__ Cf, __half* __restrict__ Ch, int ldc,
         const float* __restrict__ bias,
         const float* __restrict__ resid, int relu) {
    constexpr int ST = 40;          // halves per row (80B: banks 20r%32 distinct)
    constexpr int TS = 128*ST;      // halves per tile
    extern __shared__ __half smh[];
    __half* As = smh;               // [2][128][40]
    __half* Bs = smh + 2*TS;        // [2][128][40]

    int tid = threadIdx.x, wid = tid >> 5, lane = tid & 31;
    int g = lane >> 2, tq = lane & 3;
    int wm0 = (wid & 1) * 64;
    int wn0 = (wid >> 1) * 64;
    int row0 = blockIdx.y * 128, col0 = blockIdx.x * 128;
    int mi = lane >> 3, r8 = lane & 7;

    uint32_t sbase = (uint32_t)__cvta_generic_to_shared(smh);
    int aoff = (wm0 + (mi & 1)*8 + r8)*ST + (mi >> 1)*8;
    int boff = (wn0 + (mi >> 1)*8 + r8)*ST + (mi & 1)*8;

    auto stage = [&](int b, int kt) {
        __half* Ab = As + b*TS;
        __half* Bb = Bs + b*TS;
        int k0 = kt << 5;
        #pragma unroll
        for (int c = tid; c < 512; c += 128) {
            int m = c >> 2, ch = c & 3;
            cp16(&Ab[m*ST + ch*8], A + (size_t)(row0 + m)*lda + k0 + ch*8);
        }
        #pragma unroll
        for (int c = tid; c < 512; c += 128) {
            int n = c >> 2, ch = c & 3;
            cp16(&Bb[n*ST + ch*8], W + (size_t)(col0 + n)*K + k0 + ch*8);
        }
    };

    float acc[4][8][4];
    #pragma unroll
    for (int i = 0; i < 4; i++)
        #pragma unroll
        for (int j = 0; j < 8; j++)
            #pragma unroll
            for (int r = 0; r < 4; r++) acc[i][j][r] = 0.f;

    stage(0, 0); cp_commit();

    int NT = K >> 5;
    for (int kt = 0; kt < NT; kt++) {
        if (kt + 1 < NT) {
            stage((kt + 1) & 1, kt + 1);
            cp_commit();
            cp_wait<1>();
        } else {
            cp_wait<0>();
        }
        __syncthreads();

        uint32_t abase = sbase + (uint32_t)((kt & 1)*TS + aoff)*2;
        uint32_t bbase = sbase + (uint32_t)(2*TS + (kt & 1)*TS + boff)*2;
        #pragma unroll
        for (int ks = 0; ks < 2; ks++) {
            uint32_t a[4][4], bq[4][4];
            #pragma unroll
            for (int mt = 0; mt < 4; mt++)
                ldsm4(a[mt], abase + (uint32_t)(mt*16*ST + ks*16)*2);
            #pragma unroll
            for (int p = 0; p < 4; p++)
                ldsm4(bq[p], bbase + (uint32_t)(p*16*ST + ks*16)*2);
            #pragma unroll
            for (int mt = 0; mt < 4; mt++)
                #pragma unroll
                for (int nt = 0; nt < 8; nt++)
                    mma_f16(acc[mt][nt], a[mt], &bq[nt >> 1][(nt & 1)*2]);
        }
        __syncthreads();
    }

    // ---- epilogue ----
    #pragma unroll
    for (int mt = 0; mt < 4; mt++) {
        int m0 = row0 + wm0 + mt*16 + g;
        #pragma unroll
        for (int nt = 0; nt < 8; nt++) {
            int n = col0 + wn0 + nt*8 + 2*tq;
            float bx = 0.f, by = 0.f;
            if (bias) { bx = bias[n]; by = bias[n+1]; }
            #pragma unroll
            for (int half = 0; half < 2; half++) {
                int m = m0 + half*8;
                float vx = acc[mt][nt][half*2+0] + bx;
                float vy = acc[mt][nt][half*2+1] + by;
                size_t ci = (size_t)m * ldc + n;
                if (relu) { vx = fmaxf(vx, 0.f); vy = fmaxf(vy, 0.f); }
                if (Cf) {
                    if (resid) {
                        float2 rr = *reinterpret_cast<const float2*>(&resid[ci]);
                        vx += rr.x; vy += rr.y;
                    }
                    *reinterpret_cast<float2*>(&Cf[ci]) = make_float2(vx, vy);
                } else {
                    *reinterpret_cast<uint32_t*>(&Ch[ci]) = h2pack(vx, vy);
                }
            }
        }
    }
}

// ------------------- launcher ---------------------------------------------------
extern "C" void kernel_launch(void* const* d_in, const int* in_sizes, int n_in,
                              void* d_out, int out_size) {
    const float* x   = (const float*)d_in[0];
    const float* Wq  = (const float*)d_in[1];
    const float* Wk  = (const float*)d_in[2];
    const float* Wv  = (const float*)d_in[3];
    const float* Wo  = (const float*)d_in[4];
    const float* bo  = (const float*)d_in[5];
    const float* W1  = (const float*)d_in[6];
    const float* b1  = (const float*)d_in[7];
    const float* W2  = (const float*)d_in[8];
    const float* b2  = (const float*)d_in[9];
    const float* g1  = (const float*)d_in[10];
    const float* be1 = (const float*)d_in[11];
    const float* g2  = (const float*)d_in[12];
    const float* be2 = (const float*)d_in[13];
    float* out = (float*)d_out;

    __half *h, *qkv, *o, *h2, *ff, *wqkvT, *woT, *w1T, *w2T;
    cudaGetSymbolAddress((void**)&h,     g_h);
    cudaGetSymbolAddress((void**)&qkv,   g_qkv);
    cudaGetSymbolAddress((void**)&o,     g_o);
    cudaGetSymbolAddress((void**)&h2,    g_h2);
    cudaGetSymbolAddress((void**)&ff,    g_ff);
    cudaGetSymbolAddress((void**)&wqkvT, g_WqkvT);
    cudaGetSymbolAddress((void**)&woT,   g_WoT);
    cudaGetSymbolAddress((void**)&w1T,   g_W1T);
    cudaGetSymbolAddress((void**)&w2T,   g_W2T);

    const int FLASH_SMEM = 3 * 128 * 72 * 2;   // 55296
    const int GEMM_SMEM  = 4 * 128 * 40 * 2;   // 40960
    static int smem_set = 0;
    if (!smem_set) {
        cudaFuncSetAttribute(flash_kernel,
                             cudaFuncAttributeMaxDynamicSharedMemorySize, FLASH_SMEM);
        cudaFuncSetAttribute(mma_gemm,
                             cudaFuncAttributeMaxDynamicSharedMemorySize, GEMM_SMEM);
        smem_set = 1;
    }

    // merged weight prep + LN1
    prep_ln<<<12288 + BT_, 256>>>(Wq, Wk, Wv, Wo, W1, W2,
                                  wqkvT, woT, w1T, w2T, x, g1, be1, h);

    // qkv = h @ Wqkv  (half out)
    mma_gemm<<<dim3(S3_/128, BT_/128), 128, GEMM_SMEM>>>(
        h, C_, wqkvT, C_, nullptr, qkv, S3_, nullptr, nullptr, 0);

    // fused attention -> o (half)
    flash_kernel<<<dim3(T_/128, B_*H_), 128, FLASH_SMEM>>>(qkv, o);

    // x1 = x + o @ Wo + bo -> d_out (fp32)
    mma_gemm<<<dim3(C_/128, BT_/128), 128, GEMM_SMEM>>>(
        o, C_, woT, C_, out, nullptr, C_, bo, x, 0);

    // LN2 -> h2 (half)
    ln_kernel<<<BT_, 256>>>(out, g2, be2, h2);

    // ff = relu(h2 @ W1 + b1)  (half out)
    mma_gemm<<<dim3(FF_/128, BT_/128), 128, GEMM_SMEM>>>(
        h2, C_, w1T, C_, nullptr, ff, FF_, b1, nullptr, 1);

    // out = x1 + ff @ W2 + b2  (fp32)
    mma_gemm<<<dim3(C_/128, BT_/128), 128, GEMM_SMEM>>>(
        ff, FF_, w2T, FF_, out, nullptr, C_, b2, out, 0);
}